// round 7
// baseline (speedup 1.0000x reference)
#include <cuda_runtime.h>
#include <cuda_fp16.h>
#include <cstdint>
#include <cstddef>

// ============================================================================
// EGNN layer: h' = h + MLP_u([h, scatter_add(MLP_m([h_s, h_r, dist]))])
//
// Layer-1 of the edge MLP is linear in gathered features -> node-level GEMMs
// P = h@W1a^T, Q = h@W1b^T. Edge kernel: gather -> silu -> fp16 MMA
// (2Mx4N warp tiles, ldmatrix A, pre-packed B fragments) -> silu ->
// red.global.v2 scatter directly from accumulators.
// ============================================================================

#define DD 128
#define NMAX 50176  // >= N = 50000

__device__ __align__(16) float g_P[(size_t)NMAX * DD];
__device__ __align__(16) float g_Q[(size_t)NMAX * DD];
__device__ __align__(16) float g_agg[(size_t)NMAX * DD];
__device__ __align__(16) float g_u1[(size_t)NMAX * DD];
// W2 as fp16 mma B-fragments, lane-ordered: [nq][i(0..15)][lane(0..31)][4 u32]
__device__ __align__(16) uint32_t g_W2frag[4 * 16 * 32 * 4];

__device__ __forceinline__ float* resolve_buf(int code, const float* ext) {
    switch (code) {
        case 1: return g_P;
        case 2: return g_Q;
        case 3: return g_agg;
        case 4: return g_u1;
        default: return (float*)ext;
    }
}

// silu via single-MUFU tanh.approx: silu(x) = 0.5x(1 + tanh(x/2))
__device__ __forceinline__ float silu_f(float x) {
    float t;
    asm("tanh.approx.f32 %0, %1;" : "=f"(t) : "f"(0.5f * x));
    return 0.5f * x * (1.f + t);
}
// paired silu using tanh.approx.f16x2 (1 MUFU for 2 values)
__device__ __forceinline__ float2 silu2_f(float x0, float x1) {
    __half2 ph = __floats2half2_rn(0.5f * x0, 0.5f * x1);
    uint32_t pu = *(uint32_t*)&ph, tu;
    asm("tanh.approx.f16x2 %0, %1;" : "=r"(tu) : "r"(pu));
    float2 tf = __half22float2(*(__half2*)&tu);
    return make_float2(0.5f * x0 * (1.f + tf.x), 0.5f * x1 * (1.f + tf.y));
}
__device__ __forceinline__ float tf32r(float x) {
    uint32_t u;
    asm("cvt.rna.tf32.f32 %0, %1;" : "=r"(u) : "f"(x));
    return __uint_as_float(u);
}
__device__ __forceinline__ void mma8(float* c, const uint32_t* a, const uint32_t* b) {
    asm volatile(
        "mma.sync.aligned.m16n8k8.row.col.f32.tf32.tf32.f32 "
        "{%0,%1,%2,%3},{%4,%5,%6,%7},{%8,%9},{%0,%1,%2,%3};\n"
        : "+f"(c[0]), "+f"(c[1]), "+f"(c[2]), "+f"(c[3])
        : "r"(a[0]), "r"(a[1]), "r"(a[2]), "r"(a[3]), "r"(b[0]), "r"(b[1]));
}
__device__ __forceinline__ void mma16(float* c, const uint32_t* a, uint32_t b0, uint32_t b1) {
    asm volatile(
        "mma.sync.aligned.m16n8k16.row.col.f32.f16.f16.f32 "
        "{%0,%1,%2,%3},{%4,%5,%6,%7},{%8,%9},{%0,%1,%2,%3};\n"
        : "+f"(c[0]), "+f"(c[1]), "+f"(c[2]), "+f"(c[3])
        : "r"(a[0]), "r"(a[1]), "r"(a[2]), "r"(a[3]), "r"(b0), "r"(b1));
}

// ============================================================================
// Prep: pack W2 (fp32 [128][128]) into fp16 mma B-fragments, lane-ordered so
// the edge kernel loads them with coalesced LDG.128.
// value v = nt*16 + kc*2 + j; lane(g=ln>>2,q=ln&3): n = nq*32+nt*8+g,
// khalf = kc*16 + q*2 + j*8 -> half2(W2[n][khalf], W2[n][khalf+1])
// ============================================================================
__global__ void prep_w2frag(const float* __restrict__ W2) {
    int v = blockIdx.x * 256 + threadIdx.x;   // 0..8191, one uint32 each
    if (v >= 4 * 16 * 32 * 4) return;
    int c  = v & 3;
    int ln = (v >> 2) & 31;
    int i  = (v >> 7) & 15;
    int nq = v >> 11;
    int vv = i * 4 + c;          // 0..63
    int nt = vv >> 4;
    int kc = (vv >> 1) & 7;
    int j  = vv & 1;
    int g = ln >> 2, q = ln & 3;
    int n = nq * 32 + nt * 8 + g;
    int kh = kc * 16 + q * 2 + j * 8;
    __half2 h = __floats2half2_rn(W2[(size_t)n * 128 + kh],
                                  W2[(size_t)n * 128 + kh + 1]);
    g_W2frag[v] = *(uint32_t*)&h;
}

// ============================================================================
// Node-level GEMM (tf32): out[M,128] = epi( sum_p A_p[M,128] @ B_p^T )
// mode 0: raw; 1: silu(acc+bias); 2: acc+bias+resid.
// ============================================================================
__global__ __launch_bounds__(256) void gemm_node(
    const float* __restrict__ A0e, int a0c,
    const float* __restrict__ B0, int ldb0,
    int a1c, const float* __restrict__ B1, int ldb1,
    const float* __restrict__ bias, const float* __restrict__ resid,
    float* __restrict__ oute, int outc, int M, int mode)
{
    __shared__ float As[128][36];
    __shared__ float Bs[128][36];
    int tid = threadIdx.x;
    int warp = tid >> 5, ln = tid & 31;
    int m0 = blockIdx.x * 128;

    const float* A0 = resolve_buf(a0c, A0e);
    const float* A1 = (a1c == 0) ? nullptr : resolve_buf(a1c, nullptr);
    float* out = resolve_buf(outc, oute);

    float acc[16][4];
#pragma unroll
    for (int i = 0; i < 16; ++i) {
        acc[i][0] = 0.f; acc[i][1] = 0.f; acc[i][2] = 0.f; acc[i][3] = 0.f;
    }

    for (int p = 0; p < 2; ++p) {
        const float* A = p ? A1 : A0;
        const float* B = p ? B1 : B0;
        int ldb = p ? ldb1 : ldb0;
        if (!A) continue;
        for (int k0 = 0; k0 < 128; k0 += 32) {
#pragma unroll
            for (int i = 0; i < 4; ++i) {
                int r = (tid >> 3) + i * 32;
                int c = (tid & 7) * 4;
                float4 v = make_float4(0.f, 0.f, 0.f, 0.f);
                int gr = m0 + r;
                if (gr < M) v = *(const float4*)(A + (size_t)gr * 128 + k0 + c);
                v.x = tf32r(v.x); v.y = tf32r(v.y); v.z = tf32r(v.z); v.w = tf32r(v.w);
                *(float4*)&As[r][c] = v;
            }
#pragma unroll
            for (int i = 0; i < 4; ++i) {
                int n = (tid >> 3) + i * 32;
                int c = (tid & 7) * 4;
                const float* bp = B + (size_t)n * ldb + k0 + c;
                Bs[n][c + 0] = tf32r(bp[0]);
                Bs[n][c + 1] = tf32r(bp[1]);
                Bs[n][c + 2] = tf32r(bp[2]);
                Bs[n][c + 3] = tf32r(bp[3]);
            }
            __syncthreads();

            int srow = warp * 16 + (ln >> 2);
            int scol = ln & 3;
#pragma unroll
            for (int kk = 0; kk < 4; ++kk) {
                uint32_t a[4];
                a[0] = __float_as_uint(As[srow][kk * 8 + scol]);
                a[1] = __float_as_uint(As[srow + 8][kk * 8 + scol]);
                a[2] = __float_as_uint(As[srow][kk * 8 + scol + 4]);
                a[3] = __float_as_uint(As[srow + 8][kk * 8 + scol + 4]);
#pragma unroll
                for (int nt = 0; nt < 16; ++nt) {
                    uint32_t b[2];
                    b[0] = __float_as_uint(Bs[nt * 8 + (ln >> 2)][kk * 8 + scol]);
                    b[1] = __float_as_uint(Bs[nt * 8 + (ln >> 2)][kk * 8 + scol + 4]);
                    mma8(acc[nt], a, b);
                }
            }
            __syncthreads();
        }
    }

    int r0 = m0 + warp * 16 + (ln >> 2);
    int c0 = (ln & 3) * 2;
#pragma unroll
    for (int nt = 0; nt < 16; ++nt) {
        int col = nt * 8 + c0;
#pragma unroll
        for (int h8 = 0; h8 < 2; ++h8) {
            int row = r0 + h8 * 8;
            if (row >= M) continue;
#pragma unroll
            for (int q = 0; q < 2; ++q) {
                float v = acc[nt][h8 * 2 + q];
                int cc = col + q;
                if (mode == 1)      v = silu_f(v + bias[cc]);
                else if (mode == 2) v = v + bias[cc] + resid[(size_t)row * 128 + cc];
                out[(size_t)row * 128 + cc] = v;
            }
        }
    }
}

// ============================================================================
// Edge kernel v3: 64 edges/block, 256 threads, warps as 2M x 4N
// (warp tile = 32 edge-rows x 32 cols). fp16 mma m16n8k16.
//   A: silu(P[s]+Q[r]+d*w1c+b1) -> half As[64][136], read via ldmatrix.x4
//   B: pre-packed fragments (g_W2frag), 16 coalesced LDG.128 per warp
//   C: silu -> red.global.add.v2.f32 directly from accumulators
// ============================================================================
#define AS_LD 136   // half stride: 272B rows -> conflict-free LDSM phases

__global__ __launch_bounds__(256, 2) void edge_kernel(
    const float* __restrict__ coords,
    const int* __restrict__ ei,     // int32 (JAX downcasts int64)
    const float* __restrict__ W1, const float* __restrict__ b1,
    const float* __restrict__ b2,
    int E)
{
    __shared__ __align__(16) half As[64][AS_LD];
    __shared__ int   s_sh[64];
    __shared__ int   r_sh[64];
    __shared__ float dist_sh[64];
    __shared__ float b1s[128];
    __shared__ float w1cs[128];
    __shared__ float b2s[128];

    int tid = threadIdx.x;
    int warp = tid >> 5, ln = tid & 31;
    int mq = warp >> 2;          // 0..1 : rows [32mq, 32mq+32)
    int nq = warp & 3;           // 0..3 : cols [32nq, 32nq+32)
    int g = ln >> 2, q = ln & 3;
    int e0 = blockIdx.x * 64;

    // B fragments: 16 coalesced LDG.128 per warp (issued early, L2-resident)
    uint32_t breg[64];
    {
        const uint4* bp = (const uint4*)g_W2frag + (size_t)nq * 16 * 32 + ln;
#pragma unroll
        for (int i = 0; i < 16; ++i) {
            uint4 t = bp[i * 32];
            breg[i * 4 + 0] = t.x; breg[i * 4 + 1] = t.y;
            breg[i * 4 + 2] = t.z; breg[i * 4 + 3] = t.w;
        }
    }

    // meta
    if (tid < 64) {
        int e = e0 + tid;
        int s = 0, r = -1;
        float d = 0.f;
        if (e < E) {
            s = ei[e];
            r = ei[(size_t)E + e];
            float dx = coords[s * 3 + 0] - coords[r * 3 + 0];
            float dy = coords[s * 3 + 1] - coords[r * 3 + 1];
            float dz = coords[s * 3 + 2] - coords[r * 3 + 2];
            d = sqrtf(dx * dx + dy * dy + dz * dz);
        }
        s_sh[tid] = s; r_sh[tid] = r; dist_sh[tid] = d;
    }
    if (tid < 128) {
        b1s[tid]  = b1[tid];
        w1cs[tid] = W1[(size_t)tid * 257 + 256];
        b2s[tid]  = b2[tid];
    }
    __syncthreads();

    // gather + layer-1 + silu -> As (fp16); warp handles one edge row per iter
#pragma unroll
    for (int it = 0; it < 8; ++it) {
        int idx = tid + it * 256;
        int i = idx >> 5;
        int j = (idx & 31) * 4;
        int s = s_sh[i], r = r_sh[i];
        float2 v01 = make_float2(0.f, 0.f), v23 = make_float2(0.f, 0.f);
        if (r >= 0) {
            float d = dist_sh[i];
            float4 pv = *(const float4*)(g_P + (size_t)s * 128 + j);
            float4 qv = *(const float4*)(g_Q + (size_t)r * 128 + j);
            float x0 = pv.x + qv.x + d * w1cs[j + 0] + b1s[j + 0];
            float x1 = pv.y + qv.y + d * w1cs[j + 1] + b1s[j + 1];
            float x2 = pv.z + qv.z + d * w1cs[j + 2] + b1s[j + 2];
            float x3 = pv.w + qv.w + d * w1cs[j + 3] + b1s[j + 3];
            v01 = silu2_f(x0, x1);
            v23 = silu2_f(x2, x3);
        }
        __half2 h0 = __floats2half2_rn(v01.x, v01.y);
        __half2 h1 = __floats2half2_rn(v23.x, v23.y);
        uint2 pk = make_uint2(*(uint32_t*)&h0, *(uint32_t*)&h1);
        *(uint2*)&As[i][j] = pk;
    }
    __syncthreads();

    // MMA: acc[mt][nt] = rows [32mq+16mt, +16) x cols [32nq+8nt, +8), K=128
    float acc[2][4][4];
#pragma unroll
    for (int mt = 0; mt < 2; ++mt)
#pragma unroll
        for (int nt = 0; nt < 4; ++nt) {
            acc[mt][nt][0] = 0.f; acc[mt][nt][1] = 0.f;
            acc[mt][nt][2] = 0.f; acc[mt][nt][3] = 0.f;
        }

#pragma unroll
    for (int kc = 0; kc < 8; ++kc) {
        uint32_t a[2][4];
#pragma unroll
        for (int mt = 0; mt < 2; ++mt) {
            int lrow = mq * 32 + mt * 16 + (ln & 15);
            int lcol = kc * 16 + (ln >> 4) * 8;
            uint32_t addr = (uint32_t)__cvta_generic_to_shared(&As[lrow][lcol]);
            asm volatile(
                "ldmatrix.sync.aligned.m8n8.x4.shared.b16 {%0,%1,%2,%3}, [%4];"
                : "=r"(a[mt][0]), "=r"(a[mt][1]), "=r"(a[mt][2]), "=r"(a[mt][3])
                : "r"(addr));
        }
#pragma unroll
        for (int mt = 0; mt < 2; ++mt)
#pragma unroll
            for (int nt = 0; nt < 4; ++nt)
                mma16(acc[mt][nt], a[mt],
                      breg[nt * 16 + kc * 2], breg[nt * 16 + kc * 2 + 1]);
    }

    // epilogue: silu + vector-red scatter straight from accumulators
#pragma unroll
    for (int mt = 0; mt < 2; ++mt) {
#pragma unroll
        for (int h8 = 0; h8 < 2; ++h8) {
            int rowi = mq * 32 + mt * 16 + h8 * 8 + g;
            int r = r_sh[rowi];
#pragma unroll
            for (int nt = 0; nt < 4; ++nt) {
                int col = nq * 32 + nt * 8 + q * 2;
                float2 v = silu2_f(acc[mt][nt][h8 * 2 + 0] + b2s[col],
                                   acc[mt][nt][h8 * 2 + 1] + b2s[col + 1]);
                if (r >= 0) {
                    float* dst = g_agg + (size_t)r * 128 + col;
                    asm volatile(
                        "red.global.add.v2.f32 [%0], {%1, %2};"
                        :: "l"(dst), "f"(v.x), "f"(v.y) : "memory");
                }
            }
        }
    }
}

__global__ void zero_agg(int n4) {
    int i = blockIdx.x * 256 + threadIdx.x;
    if (i < n4) ((float4*)g_agg)[i] = make_float4(0.f, 0.f, 0.f, 0.f);
}

// ============================================================================
// Host launch: kernel launches ONLY (graph-capture safe).
// ============================================================================
extern "C" void kernel_launch(void* const* d_in, const int* in_sizes, int n_in,
                              void* d_out, int out_size)
{
    const float* h_ptr  = (const float*)d_in[0];
    const float* coords = (const float*)d_in[1];
    const int*   ei     = (const int*)d_in[2];
    const float* W1     = (const float*)d_in[3];
    const float* b1     = (const float*)d_in[4];
    const float* W2     = (const float*)d_in[5];
    const float* b2     = (const float*)d_in[6];
    const float* U1     = (const float*)d_in[7];
    const float* c1     = (const float*)d_in[8];
    const float* U2     = (const float*)d_in[9];
    const float* c2     = (const float*)d_in[10];

    int N = in_sizes[0] / 128;
    int E = in_sizes[2] / 2;
    int mt = (N + 127) / 128;

    prep_w2frag<<<32, 256>>>(W2);

    gemm_node<<<mt, 256>>>(h_ptr, 0, W1, 257, 0, nullptr, 0,
                           nullptr, nullptr, nullptr, 1, N, 0);
    gemm_node<<<mt, 256>>>(h_ptr, 0, W1 + 128, 257, 0, nullptr, 0,
                           nullptr, nullptr, nullptr, 2, N, 0);

    int n4 = N * 32;
    zero_agg<<<(n4 + 255) / 256, 256>>>(n4);

    edge_kernel<<<(E + 63) / 64, 256>>>(coords, ei, W1, b1, b2, E);

    gemm_node<<<mt, 256>>>(h_ptr, 0, U1, 256, 3, U1 + 128, 256,
                           c1, nullptr, nullptr, 4, N, 1);
    gemm_node<<<mt, 256>>>(nullptr, 4, U2, 128, 0, nullptr, 0,
                           c2, h_ptr, (float*)d_out, 0, N, 2);
}